// round 14
// baseline (speedup 1.0000x reference)
#include <cuda_runtime.h>
#include <math.h>

#define N_ATOMS 8192
#define D_DIM   128
#define K_MAX   4224
#define SPLIT_AK 9
#define TWO_PI  6.28318530717958647692f

typedef unsigned long long u64;

// ---------------- static device scratch ----------------
__device__ float2 g_csf[(size_t)K_MAX * N_ATOMS];   // [K][N] {cos,sin} fwd
__device__ float2 g_csi[(size_t)N_ATOMS * K_MAX];   // [N][K] {cos,sin} inv
__device__ u64   g_pK[SPLIT_AK][(size_t)K_MAX * D_DIM];    // {kpr,kpi} partials
__device__ float g_pA[4][(size_t)2 * K_MAX * D_DIM];       // v_pot tensor partials
__device__ float g_vpr[K_MAX * D_DIM];
__device__ float g_vpi[K_MAX * D_DIM];
__device__ float g_akp[K_MAX * D_DIM];
__device__ float g_qabs[(size_t)N_ATOMS * D_DIM];
__device__ float g_aw[(size_t)N_ATOMS * K_MAX];
__device__ float2 g_rs[N_ATOMS];                    // per-row {max, 1/sum}
__device__ float g_pDf[2][(size_t)N_ATOMS * D_DIM];

// ---------------- helpers ----------------
__device__ __forceinline__ u64 pk2(float lo, float hi) {
    u64 r; asm("mov.b64 %0,{%1,%2};" : "=l"(r) : "f"(lo), "f"(hi)); return r;
}
__device__ __forceinline__ u64 dup2(float x) { return pk2(x, x); }
__device__ __forceinline__ void fma2(u64& d, u64 a, u64 b) {
    asm("fma.rn.f32x2 %0,%1,%2,%0;" : "+l"(d) : "l"(a), "l"(b));
}
__device__ __forceinline__ float2 up2(u64 v) {
    float2 f; asm("mov.b64 {%0,%1},%2;" : "=f"(f.x), "=f"(f.y) : "l"(v)); return f;
}
__device__ __forceinline__ unsigned tf32(float x) {
    unsigned r; asm("cvt.rna.tf32.f32 %0, %1;" : "=r"(r) : "f"(x)); return r;
}
__device__ __forceinline__ void mma_tf32(float* c, const unsigned* a, const unsigned* b) {
    asm volatile("mma.sync.aligned.m16n8k8.row.col.f32.tf32.tf32.f32 "
        "{%0,%1,%2,%3}, {%4,%5,%6,%7}, {%8,%9}, {%0,%1,%2,%3};"
        : "+f"(c[0]), "+f"(c[1]), "+f"(c[2]), "+f"(c[3])
        : "r"(a[0]), "r"(a[1]), "r"(a[2]), "r"(a[3]), "r"(b[0]), "r"(b[1]));
}

// ---------------- plane-wave table helper ----------------
__device__ __forceinline__ void build_tables_one(
    float rx, float ry, float rz,
    float* exr, float* exi, float* eyr, float* eyi,
    float* ezr, float* ezi, int pitch)
{
    #pragma unroll
    for (int j = 0; j <= 12; j++) {
        float s, c;
        sincosf(TWO_PI * rx * (float)j, &s, &c);
        exr[j * pitch] = c; exi[j * pitch] = s;
    }
    #pragma unroll
    for (int j = 0; j <= 12; j++) {
        float s, c;
        sincosf(TWO_PI * ry * (float)j, &s, &c);
        eyr[(12 + j) * pitch] = c; eyi[(12 + j) * pitch] = s;
        eyr[(12 - j) * pitch] = c; eyi[(12 - j) * pitch] = -s;
    }
    #pragma unroll
    for (int j = 0; j <= 12; j++) {
        float s, c;
        sincosf(TWO_PI * rz * (float)j, &s, &c);
        ezr[(12 + j) * pitch] = c; ezi[(12 + j) * pitch] = s;
        ezr[(12 - j) * pitch] = c; ezi[(12 - j) * pitch] = -s;
    }
}

// ---------------- kernel 1a: forward E matrix [K][N], k-striped ----------
__global__ void __launch_bounds__(256) k_build_fwd(
    const float* __restrict__ pos, const float* __restrict__ cell,
    const int* __restrict__ kfwd, int K)
{
    __shared__ float exr[13][32], exi[13][32];
    __shared__ float eyr[25][32], eyi[25][32];
    __shared__ float ezr[25][32], ezi[25][32];

    const int tx = threadIdx.x, ty = threadIdx.y;
    const int n0 = blockIdx.x * 32;

    if (ty == 0) {
        int n = n0 + tx;
        float bx = cell[0], by = cell[4], bz = cell[8];
        build_tables_one(pos[n*3+0]/bx, pos[n*3+1]/by, pos[n*3+2]/bz,
                         &exr[0][tx], &exi[0][tx], &eyr[0][tx], &eyi[0][tx],
                         &ezr[0][tx], &ezi[0][tx], 32);
    }
    __syncthreads();

    for (int k = ty + 8 * blockIdx.y; k < K; k += 8 * gridDim.y) {
        int a = kfwd[3*k+0], b = kfwd[3*k+1] + 12, c = kfwd[3*k+2] + 12;
        float xr = exr[a][tx], xi = exi[a][tx];
        float yr = eyr[b][tx], yi = eyi[b][tx];
        float zr = ezr[c][tx], zi = ezi[c][tx];
        float pr = xr*yr - xi*yi, pi = xr*yi + xi*yr;
        g_csf[(size_t)k * N_ATOMS + n0 + tx] =
            make_float2(pr*zr - pi*zi, pr*zi + pi*zr);
    }
}

// ---------------- kernel 1b: inverse E matrix [N][K], k-striped ----------
__global__ void __launch_bounds__(256) k_build_inv(
    const float* __restrict__ pos, const float* __restrict__ cell,
    const int* __restrict__ kinv, int K)
{
    __shared__ float exr[13][9], exi[13][9];
    __shared__ float eyr[25][9], eyi[25][9];
    __shared__ float ezr[25][9], ezi[25][9];

    const int tx = threadIdx.x, ty = threadIdx.y;
    const int tid = tx + 32 * ty;
    const int n0 = blockIdx.x * 8;

    if (tid < 8) {
        int n = n0 + tid;
        float bx = cell[0], by = cell[4], bz = cell[8];
        build_tables_one(pos[n*3+0]/bx, pos[n*3+1]/by, pos[n*3+2]/bz,
                         &exr[0][tid], &exi[0][tid], &eyr[0][tid], &eyi[0][tid],
                         &ezr[0][tid], &ezi[0][tid], 9);
    }
    __syncthreads();

    for (int k = tx + 32 * blockIdx.y; k < K; k += 32 * gridDim.y) {
        int a = kinv[3*k+0], b = kinv[3*k+1] + 12, c = kinv[3*k+2] + 12;
        float xr = exr[a][ty], xi = exi[a][ty];
        float yr = eyr[b][ty], yi = eyi[b][ty];
        float zr = ezr[c][ty], zi = ezi[c][ty];
        float pr = xr*yr - xi*yi, pi = xr*yi + xi*yr;
        g_csi[(size_t)(n0 + ty) * K + k] =
            make_float2(pr*zr - pi*zi, pr*zi + pi*zr);
    }
}

// ---------------- kernel 1c: |q| ----------------
__global__ void k_absq(const float* __restrict__ q)
{
    int i = blockIdx.x * 256 + threadIdx.x;
    g_qabs[i] = fabsf(q[i]);
}

// ---------------- kernel 2a: k_pot scalar GEMM (fp32, f32x2) ---------------
// tile 64k x 128d; warp ty: 8 k-rows (ty+8j), lane: 4 d-cols (tx+32m).
__global__ void __launch_bounds__(256, 2) k_phaseAK(
    const float* __restrict__ kv, int K)
{
    __shared__ float s_k[32][128];  // [n][d]

    const int t  = threadIdx.x;
    const int tx = t & 31;
    const int ty = t >> 5;
    const int k0 = blockIdx.x * 64;
    const int sp = blockIdx.y;
    const int nb0 = ((256 * sp) / SPLIT_AK) * 32;
    const int nb_end = ((256 * (sp + 1)) / SPLIT_AK) * 32;

    u64 aK[8][4];
    #pragma unroll
    for (int j = 0; j < 8; j++)
        #pragma unroll
        for (int m = 0; m < 4; m++) aK[j][m] = 0ull;

    for (int nb = nb0; nb < nb_end; nb += 32) {
        u64 csr[8];
        #pragma unroll
        for (int j = 0; j < 8; j++) {
            int kl = ty + 8 * j;
            csr[j] = *(const u64*)&g_csf[(size_t)(k0 + kl) * N_ATOMS + nb + tx];
        }
        __syncthreads();
        #pragma unroll
        for (int j = 0; j < 4; j++) {
            int row = ty + 8 * j;
            *(float4*)&s_k[row][tx*4] = *(const float4*)&kv[(size_t)(nb+row)*128 + tx*4];
        }
        __syncthreads();

        #pragma unroll
        for (int nn = 0; nn < 32; nn++) {
            u64 CS[8];
            #pragma unroll
            for (int j = 0; j < 8; j++)
                CS[j] = __shfl_sync(0xffffffffu, csr[j], nn);
            #pragma unroll
            for (int m = 0; m < 4; m++) {
                u64 Kd = dup2(s_k[nn][tx + 32 * m]);
                #pragma unroll
                for (int j = 0; j < 8; j++)
                    fma2(aK[j][m], CS[j], Kd);
            }
        }
    }

    #pragma unroll
    for (int j = 0; j < 8; j++) {
        int k = k0 + ty + 8 * j;
        if (k < K) {
            #pragma unroll
            for (int m = 0; m < 4; m++)
                g_pK[sp][(size_t)k * 128 + tx + 32 * m] = aK[j][m];
        }
    }
}

// ---------------- kernel 2b: v_pot TF32 tensor GEMM -------------------------
#define MPAD 20
#define BPAD 136
__global__ void __launch_bounds__(256) k_phaseAV(
    const float* __restrict__ vv, int K)
{
    __shared__ unsigned Msm[64][MPAD];   // [2k+c][atom]
    __shared__ unsigned Bsm[16][BPAD];   // [atom][d]

    const int t    = threadIdx.x;
    const int lane = t & 31;
    const int w    = t >> 5;
    const int wm   = w >> 2;
    const int wn   = w & 3;
    const int kb   = blockIdx.x * 32;
    const int z    = blockIdx.y;
    const int nb0  = z * (N_ATOMS / 4);
    const int nbE  = nb0 + (N_ATOMS / 4);

    float acc[2][4][4];
    #pragma unroll
    for (int f = 0; f < 2; f++)
        #pragma unroll
        for (int g = 0; g < 4; g++)
            #pragma unroll
            for (int r = 0; r < 4; r++) acc[f][g][r] = 0.f;

    for (int nb = nb0; nb < nbE; nb += 16) {
        __syncthreads();
        #pragma unroll
        for (int i = 0; i < 2; i++) {
            int idx = t + 256 * i;
            int kr = idx >> 4, col = idx & 15;
            float2 cs = make_float2(0.f, 0.f);
            if (kb + kr < K)
                cs = g_csf[(size_t)(kb + kr) * N_ATOMS + nb + col];
            Msm[2 * kr][col]     = tf32(cs.x);
            Msm[2 * kr + 1][col] = tf32(cs.y);
        }
        #pragma unroll
        for (int i = 0; i < 2; i++) {
            int idx = t + 256 * i;
            int row = idx >> 5, c4 = idx & 31;
            float4 v = *(const float4*)&vv[(size_t)(nb + row) * 128 + c4 * 4];
            Bsm[row][c4*4+0] = tf32(v.x);
            Bsm[row][c4*4+1] = tf32(v.y);
            Bsm[row][c4*4+2] = tf32(v.z);
            Bsm[row][c4*4+3] = tf32(v.w);
        }
        __syncthreads();

        #pragma unroll
        for (int s = 0; s < 2; s++) {
            unsigned a[2][4];
            {
                int ac_ = s * 8 + (lane & 3);
                #pragma unroll
                for (int f = 0; f < 2; f++) {
                    int ar = wm * 32 + f * 16 + (lane >> 2);
                    a[f][0] = Msm[ar][ac_];
                    a[f][1] = Msm[ar + 8][ac_];
                    a[f][2] = Msm[ar][ac_ + 4];
                    a[f][3] = Msm[ar + 8][ac_ + 4];
                }
            }
            unsigned b[4][2];
            {
                int br = s * 8 + (lane & 3);
                #pragma unroll
                for (int g = 0; g < 4; g++) {
                    int bc = wn * 32 + g * 8 + (lane >> 2);
                    b[g][0] = Bsm[br][bc];
                    b[g][1] = Bsm[br + 4][bc];
                }
            }
            #pragma unroll
            for (int f = 0; f < 2; f++)
                #pragma unroll
                for (int g = 0; g < 4; g++)
                    mma_tf32(acc[f][g], a[f], b[g]);
        }
    }

    #pragma unroll
    for (int f = 0; f < 2; f++) {
        int row = kb * 2 + wm * 32 + f * 16 + (lane >> 2);
        #pragma unroll
        for (int g = 0; g < 4; g++) {
            int col = wn * 32 + g * 8 + 2 * (lane & 3);
            *(float2*)&g_pA[z][(size_t)row * 128 + col] =
                make_float2(acc[f][g][0], acc[f][g][1]);
            *(float2*)&g_pA[z][(size_t)(row + 8) * 128 + col] =
                make_float2(acc[f][g][2], acc[f][g][3]);
        }
    }
}

// ---------------- kernel 3: reduce splits + |k_pot| + v_pot -----------------
__global__ void k_reduceA(int K)
{
    int i = blockIdx.x * 256 + threadIdx.x;
    if (i >= K * 128) return;
    float kr = 0.f, ki = 0.f;
    #pragma unroll
    for (int s = 0; s < SPLIT_AK; s++) {
        float2 a = up2(g_pK[s][i]);
        kr += a.x; ki += a.y;
    }
    g_akp[i] = sqrtf(kr*kr + ki*ki);

    int k = i >> 7, d = i & 127;
    float vr = 0.f, vi = 0.f;
    #pragma unroll
    for (int z = 0; z < 4; z++) {
        vr += g_pA[z][(size_t)(2 * k) * 128 + d];
        vi += g_pA[z][(size_t)(2 * k + 1) * 128 + d];
    }
    g_vpr[i] = vr; g_vpi[i] = vi;
}

// ---------------- kernel 4: aw = |q| @ |k_pot|^T (128 k-cols) --------------
__global__ void __launch_bounds__(256) k_phaseB(int K)
{
    __shared__ float s_a[16][132];  // [d][n]
    __shared__ float s_b[16][136];  // [d][k]

    const int t  = threadIdx.x;
    const int tx = t & 15;          // k cols tx*8..+7
    const int ty = t >> 4;          // n rows ty*8..+7
    const int kb = blockIdx.x * 128;
    const int nb = blockIdx.y * 128;

    u64 ac[8][4];
    #pragma unroll
    for (int i = 0; i < 8; i++)
        #pragma unroll
        for (int p = 0; p < 4; p++) ac[i][p] = 0ull;

    for (int d0 = 0; d0 < 128; d0 += 16) {
        __syncthreads();
        #pragma unroll
        for (int i = 0; i < 8; i++) {
            int r = ty + 16 * i;
            s_a[tx][r] = g_qabs[(size_t)(nb + r) * 128 + d0 + tx];
        }
        #pragma unroll
        for (int i = 0; i < 8; i++) {
            int r = ty + 16 * i;
            s_b[tx][r] = (kb + r < K) ? g_akp[(kb + r) * 128 + d0 + tx] : 0.f;
        }
        __syncthreads();
        #pragma unroll
        for (int dd = 0; dd < 16; dd++) {
            ulonglong2 b0 = *(const ulonglong2*)&s_b[dd][tx * 8];
            ulonglong2 b1 = *(const ulonglong2*)&s_b[dd][tx * 8 + 4];
            float4 a0 = *(const float4*)&s_a[dd][ty * 8];
            float4 a1 = *(const float4*)&s_a[dd][ty * 8 + 4];
            u64 A;
            A = dup2(a0.x); fma2(ac[0][0],A,b0.x); fma2(ac[0][1],A,b0.y); fma2(ac[0][2],A,b1.x); fma2(ac[0][3],A,b1.y);
            A = dup2(a0.y); fma2(ac[1][0],A,b0.x); fma2(ac[1][1],A,b0.y); fma2(ac[1][2],A,b1.x); fma2(ac[1][3],A,b1.y);
            A = dup2(a0.z); fma2(ac[2][0],A,b0.x); fma2(ac[2][1],A,b0.y); fma2(ac[2][2],A,b1.x); fma2(ac[2][3],A,b1.y);
            A = dup2(a0.w); fma2(ac[3][0],A,b0.x); fma2(ac[3][1],A,b0.y); fma2(ac[3][2],A,b1.x); fma2(ac[3][3],A,b1.y);
            A = dup2(a1.x); fma2(ac[4][0],A,b0.x); fma2(ac[4][1],A,b0.y); fma2(ac[4][2],A,b1.x); fma2(ac[4][3],A,b1.y);
            A = dup2(a1.y); fma2(ac[5][0],A,b0.x); fma2(ac[5][1],A,b0.y); fma2(ac[5][2],A,b1.x); fma2(ac[5][3],A,b1.y);
            A = dup2(a1.z); fma2(ac[6][0],A,b0.x); fma2(ac[6][1],A,b0.y); fma2(ac[6][2],A,b1.x); fma2(ac[6][3],A,b1.y);
            A = dup2(a1.w); fma2(ac[7][0],A,b0.x); fma2(ac[7][1],A,b0.y); fma2(ac[7][2],A,b1.x); fma2(ac[7][3],A,b1.y);
        }
    }
    #pragma unroll
    for (int i = 0; i < 8; i++) {
        int n = nb + ty * 8 + i;
        size_t base = (size_t)n * K + kb + tx * 8;
        float vals[8];
        #pragma unroll
        for (int p = 0; p < 4; p++) {
            float2 f = up2(ac[i][p]);
            vals[2*p] = f.x; vals[2*p+1] = f.y;
        }
        #pragma unroll
        for (int j = 0; j < 8; j++)
            if (kb + tx * 8 + j < K) g_aw[base + j] = vals[j];
    }
}

// ---------------- kernel 5: row stats (max, 1/sum) only ----------------
__global__ void __launch_bounds__(256) k_rowstat(int K)
{
    __shared__ float buf[K_MAX];
    __shared__ float red[8];
    const int n = blockIdx.x;
    const int t = threadIdx.x;
    const float* row = g_aw + (size_t)n * K;

    float mx = -1e30f;
    for (int i = t; i < K; i += 256) { float v = row[i]; buf[i] = v; mx = fmaxf(mx, v); }
    #pragma unroll
    for (int o = 16; o; o >>= 1) mx = fmaxf(mx, __shfl_xor_sync(0xffffffffu, mx, o));
    if ((t & 31) == 0) red[t >> 5] = mx;
    __syncthreads();
    float gmax = red[0];
    #pragma unroll
    for (int j = 1; j < 8; j++) gmax = fmaxf(gmax, red[j]);
    __syncthreads();

    float s = 0.f;
    for (int i = t; i < K; i += 256) s += __expf(buf[i] - gmax);
    #pragma unroll
    for (int o = 16; o; o >>= 1) s += __shfl_xor_sync(0xffffffffu, s, o);
    if ((t & 31) == 0) red[t >> 5] = s;
    __syncthreads();
    if (t == 0) {
        float gsum = 0.f;
        #pragma unroll
        for (int j = 0; j < 8; j++) gsum += red[j];
        g_rs[n] = make_float2(gmax, 1.f / gsum);
    }
}

// ---------------- kernel 6: phase D TF32 GEMM, softmax fused (split-K=2) ----
#define WPAD 36
#define VPAD 136
__global__ void __launch_bounds__(256) k_phaseD(int K)
{
    __shared__ unsigned Wsm[64][WPAD];
    __shared__ unsigned Vsm[32][VPAD];
    __shared__ float2 s_rs[64];

    const int t    = threadIdx.x;
    const int lane = t & 31;
    const int w    = t >> 5;
    const int wm   = w >> 2;
    const int wn   = w & 3;
    const int n0   = blockIdx.x * 64;
    const int z    = blockIdx.y;

    if (t < 64) s_rs[t] = g_rs[n0 + t];

    const int nchunk = (K + 15) >> 4;
    const int half   = (nchunk + 1) >> 1;
    const int c_lo   = z ? half : 0;
    const int c_hi   = z ? nchunk : half;

    float acc[2][4][4];
    #pragma unroll
    for (int f = 0; f < 2; f++)
        #pragma unroll
        for (int g = 0; g < 4; g++)
            #pragma unroll
            for (int r = 0; r < 4; r++) acc[f][g][r] = 0.f;

    for (int ch = c_lo; ch < c_hi; ch++) {
        const int kbase = ch * 16;
        __syncthreads();
        #pragma unroll
        for (int i = 0; i < 4; i++) {
            int n  = (t >> 4) + 16 * i;
            int kl = t & 15;
            int k  = kbase + kl;
            float wr = 0.f, wi = 0.f;
            if (k < K) {
                size_t gi = (size_t)(n0 + n) * K + k;
                float2 rs = s_rs[n];
                float sm = __expf(g_aw[gi] - rs.x) * rs.y;
                float2 cs = g_csi[gi];
                wr = sm * cs.x; wi = sm * cs.y;
            }
            *(uint2*)&Wsm[n][2 * kl] = make_uint2(tf32(wr), tf32(wi));
        }
        #pragma unroll
        for (int i = 0; i < 4; i++) {
            int kk = (t >> 5) + 8 * i;
            int d4 = (t & 31) * 4;
            int k  = kbase + (kk >> 1);
            float4 v = make_float4(0.f, 0.f, 0.f, 0.f);
            if (k < K) {
                const float* src = (kk & 1) ? g_vpi : g_vpr;
                v = *(const float4*)&src[k * 128 + d4];
            }
            uint4 u = make_uint4(tf32(v.x), tf32(v.y), tf32(v.z), tf32(v.w));
            *(uint4*)&Vsm[kk][d4] = u;
        }
        __syncthreads();

        #pragma unroll
        for (int s = 0; s < 4; s++) {
            unsigned a[2][4];
            {
                int ac_ = s * 8 + (lane & 3);
                #pragma unroll
                for (int f = 0; f < 2; f++) {
                    int ar = wm * 32 + f * 16 + (lane >> 2);
                    a[f][0] = Wsm[ar][ac_];
                    a[f][1] = Wsm[ar + 8][ac_];
                    a[f][2] = Wsm[ar][ac_ + 4];
                    a[f][3] = Wsm[ar + 8][ac_ + 4];
                }
            }
            unsigned b[4][2];
            {
                int br = s * 8 + (lane & 3);
                #pragma unroll
                for (int g = 0; g < 4; g++) {
                    int bc = wn * 32 + g * 8 + (lane >> 2);
                    b[g][0] = Vsm[br][bc];
                    b[g][1] = Vsm[br + 4][bc];
                }
            }
            #pragma unroll
            for (int f = 0; f < 2; f++)
                #pragma unroll
                for (int g = 0; g < 4; g++)
                    mma_tf32(acc[f][g], a[f], b[g]);
        }
    }

    #pragma unroll
    for (int f = 0; f < 2; f++) {
        int row = n0 + wm * 32 + f * 16 + (lane >> 2);
        #pragma unroll
        for (int g = 0; g < 4; g++) {
            int col = wn * 32 + g * 8 + 2 * (lane & 3);
            *(float2*)&g_pDf[z][(size_t)row * 128 + col] =
                make_float2(acc[f][g][0], acc[f][g][1]);
            *(float2*)&g_pDf[z][(size_t)(row + 8) * 128 + col] =
                make_float2(acc[f][g][2], acc[f][g][3]);
        }
    }
}

// ---------------- kernel 7: phase D reduce ----------------
__global__ void k_reduceD(float* __restrict__ out)
{
    int i = blockIdx.x * 256 + threadIdx.x;
    out[i] = g_pDf[0][i] + g_pDf[1][i];
}

// ---------------- launch ----------------
extern "C" void kernel_launch(void* const* d_in, const int* in_sizes, int n_in,
                              void* d_out, int out_size)
{
    const float* q    = (const float*)d_in[0];
    const float* kvec = (const float*)d_in[1];
    const float* vvec = (const float*)d_in[2];
    const float* pos  = (const float*)d_in[3];
    const float* cell = (const float*)d_in[4];
    const int*   kfwd = (const int*)d_in[6];
    const int*   kinv = (const int*)d_in[7];
    const int K = in_sizes[6] / 3;

    dim3 b(32, 8);
    dim3 gF(N_ATOMS / 32, 4);
    k_build_fwd<<<gF, b>>>(pos, cell, kfwd, K);
    dim3 gI(N_ATOMS / 8, 4);
    k_build_inv<<<gI, b>>>(pos, cell, kinv, K);
    k_absq<<<(N_ATOMS * D_DIM) / 256, 256>>>(q);

    dim3 gAK((K + 63) / 64, SPLIT_AK);
    k_phaseAK<<<gAK, 256>>>(kvec, K);
    dim3 gAV((K + 31) / 32, 4);
    k_phaseAV<<<gAV, 256>>>(vvec, K);
    k_reduceA<<<(K * D_DIM + 255) / 256, 256>>>(K);

    dim3 gB((K + 127) / 128, N_ATOMS / 128);
    k_phaseB<<<gB, 256>>>(K);
    k_rowstat<<<N_ATOMS, 256>>>(K);

    dim3 gD(N_ATOMS / 64, 2);
    k_phaseD<<<gD, 256>>>(K);
    k_reduceD<<<(N_ATOMS * D_DIM) / 256, 256>>>((float*)d_out);
}

// round 15
// speedup vs baseline: 1.0971x; 1.0971x over previous
#include <cuda_runtime.h>
#include <math.h>

#define N_ATOMS 8192
#define D_DIM   128
#define K_MAX   4224
#define SPLIT_AK 9
#define TWO_PI  6.28318530717958647692f

typedef unsigned long long u64;

// ---------------- static device scratch ----------------
__device__ float2 g_csf[(size_t)K_MAX * N_ATOMS];   // [K][N] {cos,sin} fwd
__device__ float2 g_csi[(size_t)N_ATOMS * K_MAX];   // [N][K] {cos,sin} inv
__device__ u64   g_pK[SPLIT_AK][(size_t)K_MAX * D_DIM];    // {kpr,kpi} partials
__device__ float g_pA[4][(size_t)2 * K_MAX * D_DIM];       // v_pot tensor partials
__device__ float g_vpr[K_MAX * D_DIM];
__device__ float g_vpi[K_MAX * D_DIM];
__device__ float g_akp[K_MAX * D_DIM];
__device__ float g_qabs[(size_t)N_ATOMS * D_DIM];
__device__ float g_aw[(size_t)N_ATOMS * K_MAX];
__device__ float g_pDf[2][(size_t)N_ATOMS * D_DIM];

// ---------------- helpers ----------------
__device__ __forceinline__ u64 pk2(float lo, float hi) {
    u64 r; asm("mov.b64 %0,{%1,%2};" : "=l"(r) : "f"(lo), "f"(hi)); return r;
}
__device__ __forceinline__ u64 dup2(float x) { return pk2(x, x); }
__device__ __forceinline__ void fma2(u64& d, u64 a, u64 b) {
    asm("fma.rn.f32x2 %0,%1,%2,%0;" : "+l"(d) : "l"(a), "l"(b));
}
__device__ __forceinline__ float2 up2(u64 v) {
    float2 f; asm("mov.b64 {%0,%1},%2;" : "=f"(f.x), "=f"(f.y) : "l"(v)); return f;
}
__device__ __forceinline__ unsigned tf32(float x) {
    unsigned r; asm("cvt.rna.tf32.f32 %0, %1;" : "=r"(r) : "f"(x)); return r;
}
__device__ __forceinline__ void mma_tf32(float* c, const unsigned* a, const unsigned* b) {
    asm volatile("mma.sync.aligned.m16n8k8.row.col.f32.tf32.tf32.f32 "
        "{%0,%1,%2,%3}, {%4,%5,%6,%7}, {%8,%9}, {%0,%1,%2,%3};"
        : "+f"(c[0]), "+f"(c[1]), "+f"(c[2]), "+f"(c[3])
        : "r"(a[0]), "r"(a[1]), "r"(a[2]), "r"(a[3]), "r"(b[0]), "r"(b[1]));
}
__device__ __forceinline__ void cpasync16(unsigned sa, const void* g) {
    asm volatile("cp.async.ca.shared.global [%0], [%1], 16;" :: "r"(sa), "l"(g));
}

// ---------------- plane-wave table helper ----------------
__device__ __forceinline__ void build_tables_one(
    float rx, float ry, float rz,
    float* exr, float* exi, float* eyr, float* eyi,
    float* ezr, float* ezi, int pitch)
{
    #pragma unroll
    for (int j = 0; j <= 12; j++) {
        float s, c;
        sincosf(TWO_PI * rx * (float)j, &s, &c);
        exr[j * pitch] = c; exi[j * pitch] = s;
    }
    #pragma unroll
    for (int j = 0; j <= 12; j++) {
        float s, c;
        sincosf(TWO_PI * ry * (float)j, &s, &c);
        eyr[(12 + j) * pitch] = c; eyi[(12 + j) * pitch] = s;
        eyr[(12 - j) * pitch] = c; eyi[(12 - j) * pitch] = -s;
    }
    #pragma unroll
    for (int j = 0; j <= 12; j++) {
        float s, c;
        sincosf(TWO_PI * rz * (float)j, &s, &c);
        ezr[(12 + j) * pitch] = c; ezi[(12 + j) * pitch] = s;
        ezr[(12 - j) * pitch] = c; ezi[(12 - j) * pitch] = -s;
    }
}

// ---------------- kernel 1a: forward E matrix [K][N], k-striped ----------
__global__ void __launch_bounds__(256) k_build_fwd(
    const float* __restrict__ pos, const float* __restrict__ cell,
    const int* __restrict__ kfwd, int K)
{
    __shared__ float exr[13][32], exi[13][32];
    __shared__ float eyr[25][32], eyi[25][32];
    __shared__ float ezr[25][32], ezi[25][32];

    const int tx = threadIdx.x, ty = threadIdx.y;
    const int n0 = blockIdx.x * 32;

    if (ty == 0) {
        int n = n0 + tx;
        float bx = cell[0], by = cell[4], bz = cell[8];
        build_tables_one(pos[n*3+0]/bx, pos[n*3+1]/by, pos[n*3+2]/bz,
                         &exr[0][tx], &exi[0][tx], &eyr[0][tx], &eyi[0][tx],
                         &ezr[0][tx], &ezi[0][tx], 32);
    }
    __syncthreads();

    for (int k = ty + 8 * blockIdx.y; k < K; k += 8 * gridDim.y) {
        int a = kfwd[3*k+0], b = kfwd[3*k+1] + 12, c = kfwd[3*k+2] + 12;
        float xr = exr[a][tx], xi = exi[a][tx];
        float yr = eyr[b][tx], yi = eyi[b][tx];
        float zr = ezr[c][tx], zi = ezi[c][tx];
        float pr = xr*yr - xi*yi, pi = xr*yi + xi*yr;
        g_csf[(size_t)k * N_ATOMS + n0 + tx] =
            make_float2(pr*zr - pi*zi, pr*zi + pi*zr);
    }
}

// ---------------- kernel 1b: inverse E matrix [N][K], k-striped ----------
__global__ void __launch_bounds__(256) k_build_inv(
    const float* __restrict__ pos, const float* __restrict__ cell,
    const int* __restrict__ kinv, int K)
{
    __shared__ float exr[13][9], exi[13][9];
    __shared__ float eyr[25][9], eyi[25][9];
    __shared__ float ezr[25][9], ezi[25][9];

    const int tx = threadIdx.x, ty = threadIdx.y;
    const int tid = tx + 32 * ty;
    const int n0 = blockIdx.x * 8;

    if (tid < 8) {
        int n = n0 + tid;
        float bx = cell[0], by = cell[4], bz = cell[8];
        build_tables_one(pos[n*3+0]/bx, pos[n*3+1]/by, pos[n*3+2]/bz,
                         &exr[0][tid], &exi[0][tid], &eyr[0][tid], &eyi[0][tid],
                         &ezr[0][tid], &ezi[0][tid], 9);
    }
    __syncthreads();

    for (int k = tx + 32 * blockIdx.y; k < K; k += 32 * gridDim.y) {
        int a = kinv[3*k+0], b = kinv[3*k+1] + 12, c = kinv[3*k+2] + 12;
        float xr = exr[a][ty], xi = exi[a][ty];
        float yr = eyr[b][ty], yi = eyi[b][ty];
        float zr = ezr[c][ty], zi = ezi[c][ty];
        float pr = xr*yr - xi*yi, pi = xr*yi + xi*yr;
        g_csi[(size_t)(n0 + ty) * K + k] =
            make_float2(pr*zr - pi*zi, pr*zi + pi*zr);
    }
}

// ---------------- kernel 1c: |q| ----------------
__global__ void k_absq(const float* __restrict__ q)
{
    int i = blockIdx.x * 256 + threadIdx.x;
    g_qabs[i] = fabsf(q[i]);
}

// ---------------- kernel 2a: k_pot scalar GEMM, cp.async double-buffered ----
// tile 64k x 128d; warp ty: 8 k-rows (ty+8j), lane: 4 d-cols (tx+32m).
__global__ void __launch_bounds__(256, 2) k_phaseAK(
    const float* __restrict__ kv, int K)
{
    __shared__ float s_k[2][32][128];  // double-buffered [n][d]

    const int t  = threadIdx.x;
    const int tx = t & 31;
    const int ty = t >> 5;
    const int k0 = blockIdx.x * 64;
    const int sp = blockIdx.y;
    const int nb0 = ((256 * sp) / SPLIT_AK) * 32;
    const int nb_end = ((256 * (sp + 1)) / SPLIT_AK) * 32;
    const int ntiles = (nb_end - nb0) / 32;

    u64 aK[8][4];
    #pragma unroll
    for (int j = 0; j < 8; j++)
        #pragma unroll
        for (int m = 0; m < 4; m++) aK[j][m] = 0ull;

    // prologue: async-load tile 0 into buffer 0
    {
        #pragma unroll
        for (int j = 0; j < 4; j++) {
            int row = ty + 8 * j;
            unsigned sa = (unsigned)__cvta_generic_to_shared(&s_k[0][row][tx*4]);
            cpasync16(sa, &kv[(size_t)(nb0 + row) * 128 + tx*4]);
        }
        asm volatile("cp.async.commit_group;");
    }

    for (int it = 0; it < ntiles; it++) {
        const int nb = nb0 + it * 32;
        const int buf = it & 1;

        // issue next tile into the other buffer (safe: that buffer's last
        // readers finished before the trailing __syncthreads of iter it-1)
        if (it + 1 < ntiles) {
            #pragma unroll
            for (int j = 0; j < 4; j++) {
                int row = ty + 8 * j;
                unsigned sa = (unsigned)__cvta_generic_to_shared(&s_k[buf ^ 1][row][tx*4]);
                cpasync16(sa, &kv[(size_t)(nb + 32 + row) * 128 + tx*4]);
            }
            asm volatile("cp.async.commit_group;");
        }

        // per-lane cos/sin for this tile (independent LDGs, overlap cp.async)
        u64 csr[8];
        #pragma unroll
        for (int j = 0; j < 8; j++) {
            int kl = ty + 8 * j;
            csr[j] = *(const u64*)&g_csf[(size_t)(k0 + kl) * N_ATOMS + nb + tx];
        }

        if (it + 1 < ntiles)
            asm volatile("cp.async.wait_group 1;");
        else
            asm volatile("cp.async.wait_group 0;");
        __syncthreads();

        #pragma unroll
        for (int nn = 0; nn < 32; nn++) {
            u64 CS[8];
            #pragma unroll
            for (int j = 0; j < 8; j++)
                CS[j] = __shfl_sync(0xffffffffu, csr[j], nn);
            #pragma unroll
            for (int m = 0; m < 4; m++) {
                u64 Kd = dup2(s_k[buf][nn][tx + 32 * m]);
                #pragma unroll
                for (int j = 0; j < 8; j++)
                    fma2(aK[j][m], CS[j], Kd);
            }
        }
        __syncthreads();
    }

    #pragma unroll
    for (int j = 0; j < 8; j++) {
        int k = k0 + ty + 8 * j;
        if (k < K) {
            #pragma unroll
            for (int m = 0; m < 4; m++)
                g_pK[sp][(size_t)k * 128 + tx + 32 * m] = aK[j][m];
        }
    }
}

// ---------------- kernel 2b: v_pot TF32 tensor GEMM -------------------------
#define MPAD 20
#define BPAD 136
__global__ void __launch_bounds__(256) k_phaseAV(
    const float* __restrict__ vv, int K)
{
    __shared__ unsigned Msm[64][MPAD];   // [2k+c][atom]
    __shared__ unsigned Bsm[16][BPAD];   // [atom][d]

    const int t    = threadIdx.x;
    const int lane = t & 31;
    const int w    = t >> 5;
    const int wm   = w >> 2;
    const int wn   = w & 3;
    const int kb   = blockIdx.x * 32;
    const int z    = blockIdx.y;
    const int nb0  = z * (N_ATOMS / 4);
    const int nbE  = nb0 + (N_ATOMS / 4);

    float acc[2][4][4];
    #pragma unroll
    for (int f = 0; f < 2; f++)
        #pragma unroll
        for (int g = 0; g < 4; g++)
            #pragma unroll
            for (int r = 0; r < 4; r++) acc[f][g][r] = 0.f;

    for (int nb = nb0; nb < nbE; nb += 16) {
        __syncthreads();
        #pragma unroll
        for (int i = 0; i < 2; i++) {
            int idx = t + 256 * i;
            int kr = idx >> 4, col = idx & 15;
            float2 cs = make_float2(0.f, 0.f);
            if (kb + kr < K)
                cs = g_csf[(size_t)(kb + kr) * N_ATOMS + nb + col];
            Msm[2 * kr][col]     = tf32(cs.x);
            Msm[2 * kr + 1][col] = tf32(cs.y);
        }
        #pragma unroll
        for (int i = 0; i < 2; i++) {
            int idx = t + 256 * i;
            int row = idx >> 5, c4 = idx & 31;
            float4 v = *(const float4*)&vv[(size_t)(nb + row) * 128 + c4 * 4];
            Bsm[row][c4*4+0] = tf32(v.x);
            Bsm[row][c4*4+1] = tf32(v.y);
            Bsm[row][c4*4+2] = tf32(v.z);
            Bsm[row][c4*4+3] = tf32(v.w);
        }
        __syncthreads();

        #pragma unroll
        for (int s = 0; s < 2; s++) {
            unsigned a[2][4];
            {
                int ac_ = s * 8 + (lane & 3);
                #pragma unroll
                for (int f = 0; f < 2; f++) {
                    int ar = wm * 32 + f * 16 + (lane >> 2);
                    a[f][0] = Msm[ar][ac_];
                    a[f][1] = Msm[ar + 8][ac_];
                    a[f][2] = Msm[ar][ac_ + 4];
                    a[f][3] = Msm[ar + 8][ac_ + 4];
                }
            }
            unsigned b[4][2];
            {
                int br = s * 8 + (lane & 3);
                #pragma unroll
                for (int g = 0; g < 4; g++) {
                    int bc = wn * 32 + g * 8 + (lane >> 2);
                    b[g][0] = Bsm[br][bc];
                    b[g][1] = Bsm[br + 4][bc];
                }
            }
            #pragma unroll
            for (int f = 0; f < 2; f++)
                #pragma unroll
                for (int g = 0; g < 4; g++)
                    mma_tf32(acc[f][g], a[f], b[g]);
        }
    }

    #pragma unroll
    for (int f = 0; f < 2; f++) {
        int row = kb * 2 + wm * 32 + f * 16 + (lane >> 2);
        #pragma unroll
        for (int g = 0; g < 4; g++) {
            int col = wn * 32 + g * 8 + 2 * (lane & 3);
            *(float2*)&g_pA[z][(size_t)row * 128 + col] =
                make_float2(acc[f][g][0], acc[f][g][1]);
            *(float2*)&g_pA[z][(size_t)(row + 8) * 128 + col] =
                make_float2(acc[f][g][2], acc[f][g][3]);
        }
    }
}

// ---------------- kernel 3: reduce splits + |k_pot| + v_pot -----------------
__global__ void k_reduceA(int K)
{
    int i = blockIdx.x * 256 + threadIdx.x;
    if (i >= K * 128) return;
    float kr = 0.f, ki = 0.f;
    #pragma unroll
    for (int s = 0; s < SPLIT_AK; s++) {
        float2 a = up2(g_pK[s][i]);
        kr += a.x; ki += a.y;
    }
    g_akp[i] = sqrtf(kr*kr + ki*ki);

    int k = i >> 7, d = i & 127;
    float vr = 0.f, vi = 0.f;
    #pragma unroll
    for (int z = 0; z < 4; z++) {
        vr += g_pA[z][(size_t)(2 * k) * 128 + d];
        vi += g_pA[z][(size_t)(2 * k + 1) * 128 + d];
    }
    g_vpr[i] = vr; g_vpi[i] = vi;
}

// ---------------- kernel 4: aw = |q| @ |k_pot|^T (128 k-cols) --------------
__global__ void __launch_bounds__(256) k_phaseB(int K)
{
    __shared__ float s_a[16][132];  // [d][n]
    __shared__ float s_b[16][136];  // [d][k]

    const int t  = threadIdx.x;
    const int tx = t & 15;          // k cols tx*8..+7
    const int ty = t >> 4;          // n rows ty*8..+7
    const int kb = blockIdx.x * 128;
    const int nb = blockIdx.y * 128;

    u64 ac[8][4];
    #pragma unroll
    for (int i = 0; i < 8; i++)
        #pragma unroll
        for (int p = 0; p < 4; p++) ac[i][p] = 0ull;

    for (int d0 = 0; d0 < 128; d0 += 16) {
        __syncthreads();
        #pragma unroll
        for (int i = 0; i < 8; i++) {
            int r = ty + 16 * i;
            s_a[tx][r] = g_qabs[(size_t)(nb + r) * 128 + d0 + tx];
        }
        #pragma unroll
        for (int i = 0; i < 8; i++) {
            int r = ty + 16 * i;
            s_b[tx][r] = (kb + r < K) ? g_akp[(kb + r) * 128 + d0 + tx] : 0.f;
        }
        __syncthreads();
        #pragma unroll
        for (int dd = 0; dd < 16; dd++) {
            ulonglong2 b0 = *(const ulonglong2*)&s_b[dd][tx * 8];
            ulonglong2 b1 = *(const ulonglong2*)&s_b[dd][tx * 8 + 4];
            float4 a0 = *(const float4*)&s_a[dd][ty * 8];
            float4 a1 = *(const float4*)&s_a[dd][ty * 8 + 4];
            u64 A;
            A = dup2(a0.x); fma2(ac[0][0],A,b0.x); fma2(ac[0][1],A,b0.y); fma2(ac[0][2],A,b1.x); fma2(ac[0][3],A,b1.y);
            A = dup2(a0.y); fma2(ac[1][0],A,b0.x); fma2(ac[1][1],A,b0.y); fma2(ac[1][2],A,b1.x); fma2(ac[1][3],A,b1.y);
            A = dup2(a0.z); fma2(ac[2][0],A,b0.x); fma2(ac[2][1],A,b0.y); fma2(ac[2][2],A,b1.x); fma2(ac[2][3],A,b1.y);
            A = dup2(a0.w); fma2(ac[3][0],A,b0.x); fma2(ac[3][1],A,b0.y); fma2(ac[3][2],A,b1.x); fma2(ac[3][3],A,b1.y);
            A = dup2(a1.x); fma2(ac[4][0],A,b0.x); fma2(ac[4][1],A,b0.y); fma2(ac[4][2],A,b1.x); fma2(ac[4][3],A,b1.y);
            A = dup2(a1.y); fma2(ac[5][0],A,b0.x); fma2(ac[5][1],A,b0.y); fma2(ac[5][2],A,b1.x); fma2(ac[5][3],A,b1.y);
            A = dup2(a1.z); fma2(ac[6][0],A,b0.x); fma2(ac[6][1],A,b0.y); fma2(ac[6][2],A,b1.x); fma2(ac[6][3],A,b1.y);
            A = dup2(a1.w); fma2(ac[7][0],A,b0.x); fma2(ac[7][1],A,b0.y); fma2(ac[7][2],A,b1.x); fma2(ac[7][3],A,b1.y);
        }
    }
    #pragma unroll
    for (int i = 0; i < 8; i++) {
        int n = nb + ty * 8 + i;
        size_t base = (size_t)n * K + kb + tx * 8;
        float vals[8];
        #pragma unroll
        for (int p = 0; p < 4; p++) {
            float2 f = up2(ac[i][p]);
            vals[2*p] = f.x; vals[2*p+1] = f.y;
        }
        #pragma unroll
        for (int j = 0; j < 8; j++)
            if (kb + tx * 8 + j < K) g_aw[base + j] = vals[j];
    }
}

// ---------------- kernel 5: row softmax in place ----------------
__global__ void __launch_bounds__(256) k_softmax(int K)
{
    __shared__ float buf[K_MAX];
    __shared__ float red[8];
    const int n = blockIdx.x;
    const int t = threadIdx.x;
    float* row = g_aw + (size_t)n * K;

    float mx = -1e30f;
    for (int i = t; i < K; i += 256) { float v = row[i]; buf[i] = v; mx = fmaxf(mx, v); }
    #pragma unroll
    for (int o = 16; o; o >>= 1) mx = fmaxf(mx, __shfl_xor_sync(0xffffffffu, mx, o));
    if ((t & 31) == 0) red[t >> 5] = mx;
    __syncthreads();
    float gmax = red[0];
    #pragma unroll
    for (int j = 1; j < 8; j++) gmax = fmaxf(gmax, red[j]);
    __syncthreads();

    float s = 0.f;
    for (int i = t; i < K; i += 256) { float e = expf(buf[i] - gmax); buf[i] = e; s += e; }
    #pragma unroll
    for (int o = 16; o; o >>= 1) s += __shfl_xor_sync(0xffffffffu, s, o);
    if ((t & 31) == 0) red[t >> 5] = s;
    __syncthreads();
    float gsum = 0.f;
    #pragma unroll
    for (int j = 0; j < 8; j++) gsum += red[j];
    float inv = 1.f / gsum;
    for (int i = t; i < K; i += 256) row[i] = buf[i] * inv;
}

// ---------------- kernel 6: phase D as TF32 tensor GEMM (split-K=2) ---------
#define WPAD 36
#define VPAD 136
__global__ void __launch_bounds__(256) k_phaseD(int K)
{
    __shared__ unsigned Wsm[64][WPAD];
    __shared__ unsigned Vsm[32][VPAD];

    const int t    = threadIdx.x;
    const int lane = t & 31;
    const int w    = t >> 5;
    const int wm   = w >> 2;
    const int wn   = w & 3;
    const int n0   = blockIdx.x * 64;
    const int z    = blockIdx.y;

    const int nchunk = (K + 15) >> 4;
    const int half   = (nchunk + 1) >> 1;
    const int c_lo   = z ? half : 0;
    const int c_hi   = z ? nchunk : half;

    float acc[2][4][4];
    #pragma unroll
    for (int f = 0; f < 2; f++)
        #pragma unroll
        for (int g = 0; g < 4; g++)
            #pragma unroll
            for (int r = 0; r < 4; r++) acc[f][g][r] = 0.f;

    for (int ch = c_lo; ch < c_hi; ch++) {
        const int kbase = ch * 16;
        __syncthreads();
        #pragma unroll
        for (int i = 0; i < 4; i++) {
            int n  = (t >> 4) + 16 * i;
            int kl = t & 15;
            int k  = kbase + kl;
            float wr = 0.f, wi = 0.f;
            if (k < K) {
                size_t gi = (size_t)(n0 + n) * K + k;
                float sm = g_aw[gi];
                float2 cs = g_csi[gi];
                wr = sm * cs.x; wi = sm * cs.y;
            }
            *(uint2*)&Wsm[n][2 * kl] = make_uint2(tf32(wr), tf32(wi));
        }
        #pragma unroll
        for (int i = 0; i < 4; i++) {
            int kk = (t >> 5) + 8 * i;
            int d4 = (t & 31) * 4;
            int k  = kbase + (kk >> 1);
            float4 v = make_float4(0.f, 0.f, 0.f, 0.f);
            if (k < K) {
                const float* src = (kk & 1) ? g_vpi : g_vpr;
                v = *(const float4*)&src[k * 128 + d4];
            }
            uint4 u = make_uint4(tf32(v.x), tf32(v.y), tf32(v.z), tf32(v.w));
            *(uint4*)&Vsm[kk][d4] = u;
        }
        __syncthreads();

        #pragma unroll
        for (int s = 0; s < 4; s++) {
            unsigned a[2][4];
            {
                int ac_ = s * 8 + (lane & 3);
                #pragma unroll
                for (int f = 0; f < 2; f++) {
                    int ar = wm * 32 + f * 16 + (lane >> 2);
                    a[f][0] = Wsm[ar][ac_];
                    a[f][1] = Wsm[ar + 8][ac_];
                    a[f][2] = Wsm[ar][ac_ + 4];
                    a[f][3] = Wsm[ar + 8][ac_ + 4];
                }
            }
            unsigned b[4][2];
            {
                int br = s * 8 + (lane & 3);
                #pragma unroll
                for (int g = 0; g < 4; g++) {
                    int bc = wn * 32 + g * 8 + (lane >> 2);
                    b[g][0] = Vsm[br][bc];
                    b[g][1] = Vsm[br + 4][bc];
                }
            }
            #pragma unroll
            for (int f = 0; f < 2; f++)
                #pragma unroll
                for (int g = 0; g < 4; g++)
                    mma_tf32(acc[f][g], a[f], b[g]);
        }
    }

    #pragma unroll
    for (int f = 0; f < 2; f++) {
        int row = n0 + wm * 32 + f * 16 + (lane >> 2);
        #pragma unroll
        for (int g = 0; g < 4; g++) {
            int col = wn * 32 + g * 8 + 2 * (lane & 3);
            *(float2*)&g_pDf[z][(size_t)row * 128 + col] =
                make_float2(acc[f][g][0], acc[f][g][1]);
            *(float2*)&g_pDf[z][(size_t)(row + 8) * 128 + col] =
                make_float2(acc[f][g][2], acc[f][g][3]);
        }
    }
}

// ---------------- kernel 7: phase D reduce ----------------
__global__ void k_reduceD(float* __restrict__ out)
{
    int i = blockIdx.x * 256 + threadIdx.x;
    out[i] = g_pDf[0][i] + g_pDf[1][i];
}

// ---------------- launch ----------------
extern "C" void kernel_launch(void* const* d_in, const int* in_sizes, int n_in,
                              void* d_out, int out_size)
{
    const float* q    = (const float*)d_in[0];
    const float* kvec = (const float*)d_in[1];
    const float* vvec = (const float*)d_in[2];
    const float* pos  = (const float*)d_in[3];
    const float* cell = (const float*)d_in[4];
    const int*   kfwd = (const int*)d_in[6];
    const int*   kinv = (const int*)d_in[7];
    const int K = in_sizes[6] / 3;

    dim3 b(32, 8);
    dim3 gF(N_ATOMS / 32, 4);
    k_build_fwd<<<gF, b>>>(pos, cell, kfwd, K);
    dim3 gI(N_ATOMS / 8, 4);
    k_build_inv<<<gI, b>>>(pos, cell, kinv, K);
    k_absq<<<(N_ATOMS * D_DIM) / 256, 256>>>(q);

    dim3 gAK((K + 63) / 64, SPLIT_AK);
    k_phaseAK<<<gAK, 256>>>(kvec, K);
    dim3 gAV((K + 31) / 32, 4);
    k_phaseAV<<<gAV, 256>>>(vvec, K);
    k_reduceA<<<(K * D_DIM + 255) / 256, 256>>>(K);

    dim3 gB((K + 127) / 128, N_ATOMS / 128);
    k_phaseB<<<gB, 256>>>(K);
    k_softmax<<<N_ATOMS, 256>>>(K);

    dim3 gD(N_ATOMS / 64, 2);
    k_phaseD<<<gD, 256>>>(K);
    k_reduceD<<<(N_ATOMS * D_DIM) / 256, 256>>>((float*)d_out);
}

// round 16
// speedup vs baseline: 1.1978x; 1.0917x over previous
#include <cuda_runtime.h>
#include <math.h>

#define N_ATOMS 8192
#define D_DIM   128
#define K_MAX   4224
#define SPLIT_AK 9
#define TWO_PI  6.28318530717958647692f

typedef unsigned long long u64;

// ---------------- static device scratch ----------------
__device__ float2 g_csf[(size_t)K_MAX * N_ATOMS];   // [K][N] {cos,sin} fwd
__device__ u64   g_pK[SPLIT_AK][(size_t)K_MAX * D_DIM];    // {kpr,kpi} partials
__device__ float g_pA[4][(size_t)2 * K_MAX * D_DIM];       // v_pot tensor partials
__device__ float g_vpr[K_MAX * D_DIM];
__device__ float g_vpi[K_MAX * D_DIM];
__device__ float g_akp[K_MAX * D_DIM];
__device__ float g_qabs[(size_t)N_ATOMS * D_DIM];
__device__ float g_aw[(size_t)N_ATOMS * K_MAX];
__device__ float g_pDf[2][(size_t)N_ATOMS * D_DIM];

// ---------------- helpers ----------------
__device__ __forceinline__ u64 pk2(float lo, float hi) {
    u64 r; asm("mov.b64 %0,{%1,%2};" : "=l"(r) : "f"(lo), "f"(hi)); return r;
}
__device__ __forceinline__ u64 dup2(float x) { return pk2(x, x); }
__device__ __forceinline__ void fma2(u64& d, u64 a, u64 b) {
    asm("fma.rn.f32x2 %0,%1,%2,%0;" : "+l"(d) : "l"(a), "l"(b));
}
__device__ __forceinline__ float2 up2(u64 v) {
    float2 f; asm("mov.b64 {%0,%1},%2;" : "=f"(f.x), "=f"(f.y) : "l"(v)); return f;
}
__device__ __forceinline__ unsigned tf32(float x) {
    unsigned r; asm("cvt.rna.tf32.f32 %0, %1;" : "=r"(r) : "f"(x)); return r;
}
__device__ __forceinline__ void mma_tf32(float* c, const unsigned* a, const unsigned* b) {
    asm volatile("mma.sync.aligned.m16n8k8.row.col.f32.tf32.tf32.f32 "
        "{%0,%1,%2,%3}, {%4,%5,%6,%7}, {%8,%9}, {%0,%1,%2,%3};"
        : "+f"(c[0]), "+f"(c[1]), "+f"(c[2]), "+f"(c[3])
        : "r"(a[0]), "r"(a[1]), "r"(a[2]), "r"(a[3]), "r"(b[0]), "r"(b[1]));
}
__device__ __forceinline__ void cpasync16(unsigned sa, const void* g) {
    asm volatile("cp.async.ca.shared.global [%0], [%1], 16;" :: "r"(sa), "l"(g));
}

// ---------------- plane-wave table helper ----------------
__device__ __forceinline__ void build_tables_one(
    float rx, float ry, float rz,
    float* exr, float* exi, float* eyr, float* eyi,
    float* ezr, float* ezi, int pitch)
{
    #pragma unroll
    for (int j = 0; j <= 12; j++) {
        float s, c;
        sincosf(TWO_PI * rx * (float)j, &s, &c);
        exr[j * pitch] = c; exi[j * pitch] = s;
    }
    #pragma unroll
    for (int j = 0; j <= 12; j++) {
        float s, c;
        sincosf(TWO_PI * ry * (float)j, &s, &c);
        eyr[(12 + j) * pitch] = c; eyi[(12 + j) * pitch] = s;
        eyr[(12 - j) * pitch] = c; eyi[(12 - j) * pitch] = -s;
    }
    #pragma unroll
    for (int j = 0; j <= 12; j++) {
        float s, c;
        sincosf(TWO_PI * rz * (float)j, &s, &c);
        ezr[(12 + j) * pitch] = c; ezi[(12 + j) * pitch] = s;
        ezr[(12 - j) * pitch] = c; ezi[(12 - j) * pitch] = -s;
    }
}

// ---------------- kernel 1a: forward E matrix [K][N], k-striped ----------
__global__ void __launch_bounds__(256) k_build_fwd(
    const float* __restrict__ pos, const float* __restrict__ cell,
    const int* __restrict__ kfwd, int K)
{
    __shared__ float exr[13][32], exi[13][32];
    __shared__ float eyr[25][32], eyi[25][32];
    __shared__ float ezr[25][32], ezi[25][32];

    const int tx = threadIdx.x, ty = threadIdx.y;
    const int n0 = blockIdx.x * 32;

    if (ty == 0) {
        int n = n0 + tx;
        float bx = cell[0], by = cell[4], bz = cell[8];
        build_tables_one(pos[n*3+0]/bx, pos[n*3+1]/by, pos[n*3+2]/bz,
                         &exr[0][tx], &exi[0][tx], &eyr[0][tx], &eyi[0][tx],
                         &ezr[0][tx], &ezi[0][tx], 32);
    }
    __syncthreads();

    for (int k = ty + 8 * blockIdx.y; k < K; k += 8 * gridDim.y) {
        int a = kfwd[3*k+0], b = kfwd[3*k+1] + 12, c = kfwd[3*k+2] + 12;
        float xr = exr[a][tx], xi = exi[a][tx];
        float yr = eyr[b][tx], yi = eyi[b][tx];
        float zr = ezr[c][tx], zi = ezi[c][tx];
        float pr = xr*yr - xi*yi, pi = xr*yi + xi*yr;
        g_csf[(size_t)k * N_ATOMS + n0 + tx] =
            make_float2(pr*zr - pi*zi, pr*zi + pi*zr);
    }
}

// ---------------- kernel 1c: |q| ----------------
__global__ void k_absq(const float* __restrict__ q)
{
    int i = blockIdx.x * 256 + threadIdx.x;
    g_qabs[i] = fabsf(q[i]);
}

// ---------------- kernel 2a: k_pot scalar GEMM, cp.async double-buffered ----
__global__ void __launch_bounds__(256, 2) k_phaseAK(
    const float* __restrict__ kv, int K)
{
    __shared__ float s_k[2][32][128];

    const int t  = threadIdx.x;
    const int tx = t & 31;
    const int ty = t >> 5;
    const int k0 = blockIdx.x * 64;
    const int sp = blockIdx.y;
    const int nb0 = ((256 * sp) / SPLIT_AK) * 32;
    const int nb_end = ((256 * (sp + 1)) / SPLIT_AK) * 32;
    const int ntiles = (nb_end - nb0) / 32;

    u64 aK[8][4];
    #pragma unroll
    for (int j = 0; j < 8; j++)
        #pragma unroll
        for (int m = 0; m < 4; m++) aK[j][m] = 0ull;

    {
        #pragma unroll
        for (int j = 0; j < 4; j++) {
            int row = ty + 8 * j;
            unsigned sa = (unsigned)__cvta_generic_to_shared(&s_k[0][row][tx*4]);
            cpasync16(sa, &kv[(size_t)(nb0 + row) * 128 + tx*4]);
        }
        asm volatile("cp.async.commit_group;");
    }

    for (int it = 0; it < ntiles; it++) {
        const int nb = nb0 + it * 32;
        const int buf = it & 1;

        if (it + 1 < ntiles) {
            #pragma unroll
            for (int j = 0; j < 4; j++) {
                int row = ty + 8 * j;
                unsigned sa = (unsigned)__cvta_generic_to_shared(&s_k[buf ^ 1][row][tx*4]);
                cpasync16(sa, &kv[(size_t)(nb + 32 + row) * 128 + tx*4]);
            }
            asm volatile("cp.async.commit_group;");
        }

        u64 csr[8];
        #pragma unroll
        for (int j = 0; j < 8; j++) {
            int kl = ty + 8 * j;
            csr[j] = *(const u64*)&g_csf[(size_t)(k0 + kl) * N_ATOMS + nb + tx];
        }

        if (it + 1 < ntiles)
            asm volatile("cp.async.wait_group 1;");
        else
            asm volatile("cp.async.wait_group 0;");
        __syncthreads();

        #pragma unroll
        for (int nn = 0; nn < 32; nn++) {
            u64 CS[8];
            #pragma unroll
            for (int j = 0; j < 8; j++)
                CS[j] = __shfl_sync(0xffffffffu, csr[j], nn);
            #pragma unroll
            for (int m = 0; m < 4; m++) {
                u64 Kd = dup2(s_k[buf][nn][tx + 32 * m]);
                #pragma unroll
                for (int j = 0; j < 8; j++)
                    fma2(aK[j][m], CS[j], Kd);
            }
        }
        __syncthreads();
    }

    #pragma unroll
    for (int j = 0; j < 8; j++) {
        int k = k0 + ty + 8 * j;
        if (k < K) {
            #pragma unroll
            for (int m = 0; m < 4; m++)
                g_pK[sp][(size_t)k * 128 + tx + 32 * m] = aK[j][m];
        }
    }
}

// ---------------- kernel 2b: v_pot TF32 tensor GEMM -------------------------
#define MPAD 20
#define BPAD 136
__global__ void __launch_bounds__(256) k_phaseAV(
    const float* __restrict__ vv, int K)
{
    __shared__ unsigned Msm[64][MPAD];
    __shared__ unsigned Bsm[16][BPAD];

    const int t    = threadIdx.x;
    const int lane = t & 31;
    const int w    = t >> 5;
    const int wm   = w >> 2;
    const int wn   = w & 3;
    const int kb   = blockIdx.x * 32;
    const int z    = blockIdx.y;
    const int nb0  = z * (N_ATOMS / 4);
    const int nbE  = nb0 + (N_ATOMS / 4);

    float acc[2][4][4];
    #pragma unroll
    for (int f = 0; f < 2; f++)
        #pragma unroll
        for (int g = 0; g < 4; g++)
            #pragma unroll
            for (int r = 0; r < 4; r++) acc[f][g][r] = 0.f;

    for (int nb = nb0; nb < nbE; nb += 16) {
        __syncthreads();
        #pragma unroll
        for (int i = 0; i < 2; i++) {
            int idx = t + 256 * i;
            int kr = idx >> 4, col = idx & 15;
            float2 cs = make_float2(0.f, 0.f);
            if (kb + kr < K)
                cs = g_csf[(size_t)(kb + kr) * N_ATOMS + nb + col];
            Msm[2 * kr][col]     = tf32(cs.x);
            Msm[2 * kr + 1][col] = tf32(cs.y);
        }
        #pragma unroll
        for (int i = 0; i < 2; i++) {
            int idx = t + 256 * i;
            int row = idx >> 5, c4 = idx & 31;
            float4 v = *(const float4*)&vv[(size_t)(nb + row) * 128 + c4 * 4];
            Bsm[row][c4*4+0] = tf32(v.x);
            Bsm[row][c4*4+1] = tf32(v.y);
            Bsm[row][c4*4+2] = tf32(v.z);
            Bsm[row][c4*4+3] = tf32(v.w);
        }
        __syncthreads();

        #pragma unroll
        for (int s = 0; s < 2; s++) {
            unsigned a[2][4];
            {
                int ac_ = s * 8 + (lane & 3);
                #pragma unroll
                for (int f = 0; f < 2; f++) {
                    int ar = wm * 32 + f * 16 + (lane >> 2);
                    a[f][0] = Msm[ar][ac_];
                    a[f][1] = Msm[ar + 8][ac_];
                    a[f][2] = Msm[ar][ac_ + 4];
                    a[f][3] = Msm[ar + 8][ac_ + 4];
                }
            }
            unsigned b[4][2];
            {
                int br = s * 8 + (lane & 3);
                #pragma unroll
                for (int g = 0; g < 4; g++) {
                    int bc = wn * 32 + g * 8 + (lane >> 2);
                    b[g][0] = Bsm[br][bc];
                    b[g][1] = Bsm[br + 4][bc];
                }
            }
            #pragma unroll
            for (int f = 0; f < 2; f++)
                #pragma unroll
                for (int g = 0; g < 4; g++)
                    mma_tf32(acc[f][g], a[f], b[g]);
        }
    }

    #pragma unroll
    for (int f = 0; f < 2; f++) {
        int row = kb * 2 + wm * 32 + f * 16 + (lane >> 2);
        #pragma unroll
        for (int g = 0; g < 4; g++) {
            int col = wn * 32 + g * 8 + 2 * (lane & 3);
            *(float2*)&g_pA[z][(size_t)row * 128 + col] =
                make_float2(acc[f][g][0], acc[f][g][1]);
            *(float2*)&g_pA[z][(size_t)(row + 8) * 128 + col] =
                make_float2(acc[f][g][2], acc[f][g][3]);
        }
    }
}

// ---------------- kernel 3: reduce splits + |k_pot| + v_pot -----------------
__global__ void k_reduceA(int K)
{
    int i = blockIdx.x * 256 + threadIdx.x;
    if (i >= K * 128) return;
    float kr = 0.f, ki = 0.f;
    #pragma unroll
    for (int s = 0; s < SPLIT_AK; s++) {
        float2 a = up2(g_pK[s][i]);
        kr += a.x; ki += a.y;
    }
    g_akp[i] = sqrtf(kr*kr + ki*ki);

    int k = i >> 7, d = i & 127;
    float vr = 0.f, vi = 0.f;
    #pragma unroll
    for (int z = 0; z < 4; z++) {
        vr += g_pA[z][(size_t)(2 * k) * 128 + d];
        vi += g_pA[z][(size_t)(2 * k + 1) * 128 + d];
    }
    g_vpr[i] = vr; g_vpi[i] = vi;
}

// ---------------- kernel 4: aw = |q| @ |k_pot|^T (128 k-cols) --------------
__global__ void __launch_bounds__(256) k_phaseB(int K)
{
    __shared__ float s_a[16][132];
    __shared__ float s_b[16][136];

    const int t  = threadIdx.x;
    const int tx = t & 15;
    const int ty = t >> 4;
    const int kb = blockIdx.x * 128;
    const int nb = blockIdx.y * 128;

    u64 ac[8][4];
    #pragma unroll
    for (int i = 0; i < 8; i++)
        #pragma unroll
        for (int p = 0; p < 4; p++) ac[i][p] = 0ull;

    for (int d0 = 0; d0 < 128; d0 += 16) {
        __syncthreads();
        #pragma unroll
        for (int i = 0; i < 8; i++) {
            int r = ty + 16 * i;
            s_a[tx][r] = g_qabs[(size_t)(nb + r) * 128 + d0 + tx];
        }
        #pragma unroll
        for (int i = 0; i < 8; i++) {
            int r = ty + 16 * i;
            s_b[tx][r] = (kb + r < K) ? g_akp[(kb + r) * 128 + d0 + tx] : 0.f;
        }
        __syncthreads();
        #pragma unroll
        for (int dd = 0; dd < 16; dd++) {
            ulonglong2 b0 = *(const ulonglong2*)&s_b[dd][tx * 8];
            ulonglong2 b1 = *(const ulonglong2*)&s_b[dd][tx * 8 + 4];
            float4 a0 = *(const float4*)&s_a[dd][ty * 8];
            float4 a1 = *(const float4*)&s_a[dd][ty * 8 + 4];
            u64 A;
            A = dup2(a0.x); fma2(ac[0][0],A,b0.x); fma2(ac[0][1],A,b0.y); fma2(ac[0][2],A,b1.x); fma2(ac[0][3],A,b1.y);
            A = dup2(a0.y); fma2(ac[1][0],A,b0.x); fma2(ac[1][1],A,b0.y); fma2(ac[1][2],A,b1.x); fma2(ac[1][3],A,b1.y);
            A = dup2(a0.z); fma2(ac[2][0],A,b0.x); fma2(ac[2][1],A,b0.y); fma2(ac[2][2],A,b1.x); fma2(ac[2][3],A,b1.y);
            A = dup2(a0.w); fma2(ac[3][0],A,b0.x); fma2(ac[3][1],A,b0.y); fma2(ac[3][2],A,b1.x); fma2(ac[3][3],A,b1.y);
            A = dup2(a1.x); fma2(ac[4][0],A,b0.x); fma2(ac[4][1],A,b0.y); fma2(ac[4][2],A,b1.x); fma2(ac[4][3],A,b1.y);
            A = dup2(a1.y); fma2(ac[5][0],A,b0.x); fma2(ac[5][1],A,b0.y); fma2(ac[5][2],A,b1.x); fma2(ac[5][3],A,b1.y);
            A = dup2(a1.z); fma2(ac[6][0],A,b0.x); fma2(ac[6][1],A,b0.y); fma2(ac[6][2],A,b1.x); fma2(ac[6][3],A,b1.y);
            A = dup2(a1.w); fma2(ac[7][0],A,b0.x); fma2(ac[7][1],A,b0.y); fma2(ac[7][2],A,b1.x); fma2(ac[7][3],A,b1.y);
        }
    }
    #pragma unroll
    for (int i = 0; i < 8; i++) {
        int n = nb + ty * 8 + i;
        size_t base = (size_t)n * K + kb + tx * 8;
        float vals[8];
        #pragma unroll
        for (int p = 0; p < 4; p++) {
            float2 f = up2(ac[i][p]);
            vals[2*p] = f.x; vals[2*p+1] = f.y;
        }
        #pragma unroll
        for (int j = 0; j < 8; j++)
            if (kb + tx * 8 + j < K) g_aw[base + j] = vals[j];
    }
}

// ---------------- kernel 5: row softmax in place ----------------
__global__ void __launch_bounds__(256) k_softmax(int K)
{
    __shared__ float buf[K_MAX];
    __shared__ float red[8];
    const int n = blockIdx.x;
    const int t = threadIdx.x;
    float* row = g_aw + (size_t)n * K;

    float mx = -1e30f;
    for (int i = t; i < K; i += 256) { float v = row[i]; buf[i] = v; mx = fmaxf(mx, v); }
    #pragma unroll
    for (int o = 16; o; o >>= 1) mx = fmaxf(mx, __shfl_xor_sync(0xffffffffu, mx, o));
    if ((t & 31) == 0) red[t >> 5] = mx;
    __syncthreads();
    float gmax = red[0];
    #pragma unroll
    for (int j = 1; j < 8; j++) gmax = fmaxf(gmax, red[j]);
    __syncthreads();

    float s = 0.f;
    for (int i = t; i < K; i += 256) { float e = expf(buf[i] - gmax); buf[i] = e; s += e; }
    #pragma unroll
    for (int o = 16; o; o >>= 1) s += __shfl_xor_sync(0xffffffffu, s, o);
    if ((t & 31) == 0) red[t >> 5] = s;
    __syncthreads();
    float gsum = 0.f;
    #pragma unroll
    for (int j = 0; j < 8; j++) gsum += red[j];
    float inv = 1.f / gsum;
    for (int i = t; i < K; i += 256) row[i] = buf[i] * inv;
}

// ---------------- kernel 6: phase D TF32 GEMM, eik_i generated inline -------
// block tile 32n x 128d; warps 2(m:16 rows) x 4(n:32 cols); k-chunk 16.
// Inverse plane waves built from per-atom smem tables (no g_csi tensor).
#define WPAD 36
#define VPAD 136
__global__ void __launch_bounds__(256) k_phaseD(
    const float* __restrict__ pos, const float* __restrict__ cell,
    const int* __restrict__ kinv, int K)
{
    __shared__ float txr[32][14], txi[32][14];
    __shared__ float tyr[32][26], tyi[32][26];
    __shared__ float tzr[32][26], tzi[32][26];
    __shared__ unsigned Wsm[32][WPAD];
    __shared__ unsigned Vsm[32][VPAD];

    const int t    = threadIdx.x;
    const int lane = t & 31;
    const int w    = t >> 5;
    const int wm   = w >> 2;        // 0..1 -> rows wm*16..+15
    const int wn   = w & 3;         // 0..3 -> cols wn*32..+31
    const int n0   = blockIdx.x * 32;
    const int z    = blockIdx.y;

    // build per-atom inverse-phase tables (row-major for conflict-free lookups)
    if (t < 32) {
        int n = n0 + t;
        float bx = cell[0], by = cell[4], bz = cell[8];
        float rx = pos[n*3+0] / bx, ry = pos[n*3+1] / by, rz = pos[n*3+2] / bz;
        #pragma unroll
        for (int j = 0; j <= 12; j++) {
            float s, c;
            sincosf(TWO_PI * rx * (float)j, &s, &c);
            txr[t][j] = c; txi[t][j] = s;
        }
        #pragma unroll
        for (int j = 0; j <= 12; j++) {
            float s, c;
            sincosf(TWO_PI * ry * (float)j, &s, &c);
            tyr[t][12 + j] = c; tyi[t][12 + j] = s;
            tyr[t][12 - j] = c; tyi[t][12 - j] = -s;
        }
        #pragma unroll
        for (int j = 0; j <= 12; j++) {
            float s, c;
            sincosf(TWO_PI * rz * (float)j, &s, &c);
            tzr[t][12 + j] = c; tzi[t][12 + j] = s;
            tzr[t][12 - j] = c; tzi[t][12 - j] = -s;
        }
    }
    __syncthreads();

    const int nchunk = (K + 15) >> 4;
    const int half   = (nchunk + 1) >> 1;
    const int c_lo   = z ? half : 0;
    const int c_hi   = z ? nchunk : half;

    float acc[4][4];
    #pragma unroll
    for (int g = 0; g < 4; g++)
        #pragma unroll
        for (int r = 0; r < 4; r++) acc[g][r] = 0.f;

    for (int ch = c_lo; ch < c_hi; ch++) {
        const int kbase = ch * 16;
        __syncthreads();
        // W fill: 32 n-rows x 16 k; eik_i computed from tables
        #pragma unroll
        for (int i = 0; i < 2; i++) {
            int idx = t + 256 * i;
            int n  = idx >> 4;
            int kl = idx & 15;
            int k  = kbase + kl;
            float wr = 0.f, wi = 0.f;
            if (k < K) {
                int a = kinv[3*k+0], b = kinv[3*k+1] + 12, c = kinv[3*k+2] + 12;
                float xr = txr[n][a], xi = txi[n][a];
                float yr = tyr[n][b], yi = tyi[n][b];
                float zr = tzr[n][c], zi = tzi[n][c];
                float pr = xr*yr - xi*yi, pi = xr*yi + xi*yr;
                float er = pr*zr - pi*zi, ei = pr*zi + pi*zr;
                float sm = g_aw[(size_t)(n0 + n) * K + k];
                wr = sm * er; wi = sm * ei;
            }
            *(uint2*)&Wsm[n][2 * kl] = make_uint2(tf32(wr), tf32(wi));
        }
        // V fill: 32 kk x 128 d
        #pragma unroll
        for (int i = 0; i < 4; i++) {
            int kk = (t >> 5) + 8 * i;
            int d4 = (t & 31) * 4;
            int k  = kbase + (kk >> 1);
            float4 v = make_float4(0.f, 0.f, 0.f, 0.f);
            if (k < K) {
                const float* src = (kk & 1) ? g_vpi : g_vpr;
                v = *(const float4*)&src[k * 128 + d4];
            }
            uint4 u = make_uint4(tf32(v.x), tf32(v.y), tf32(v.z), tf32(v.w));
            *(uint4*)&Vsm[kk][d4] = u;
        }
        __syncthreads();

        #pragma unroll
        for (int s = 0; s < 4; s++) {
            unsigned a[4];
            {
                int ac_ = s * 8 + (lane & 3);
                int ar = wm * 16 + (lane >> 2);
                a[0] = Wsm[ar][ac_];
                a[1] = Wsm[ar + 8][ac_];
                a[2] = Wsm[ar][ac_ + 4];
                a[3] = Wsm[ar + 8][ac_ + 4];
            }
            unsigned b[4][2];
            {
                int br = s * 8 + (lane & 3);
                #pragma unroll
                for (int g = 0; g < 4; g++) {
                    int bc = wn * 32 + g * 8 + (lane >> 2);
                    b[g][0] = Vsm[br][bc];
                    b[g][1] = Vsm[br + 4][bc];
                }
            }
            #pragma unroll
            for (int g = 0; g < 4; g++)
                mma_tf32(acc[g], a, b[g]);
        }
    }

    {
        int row = n0 + wm * 16 + (lane >> 2);
        #pragma unroll
        for (int g = 0; g < 4; g++) {
            int col = wn * 32 + g * 8 + 2 * (lane & 3);
            *(float2*)&g_pDf[z][(size_t)row * 128 + col] =
                make_float2(acc[g][0], acc[g][1]);
            *(float2*)&g_pDf[z][(size_t)(row + 8) * 128 + col] =
                make_float2(acc[g][2], acc[g][3]);
        }
    }
}

// ---------------- kernel 7: phase D reduce ----------------
__global__ void k_reduceD(float* __restrict__ out)
{
    int i = blockIdx.x * 256 + threadIdx.x;
    out[i] = g_pDf[0][i] + g_pDf[1][i];
}

// ---------------- launch ----------------
extern "C" void kernel_launch(void* const* d_in, const int* in_sizes, int n_in,
                              void* d_out, int out_size)
{
    const float* q    = (const float*)d_in[0];
    const float* kvec = (const float*)d_in[1];
    const float* vvec = (const float*)d_in[2];
    const float* pos  = (const float*)d_in[3];
    const float* cell = (const float*)d_in[4];
    const int*   kfwd = (const int*)d_in[6];
    const int*   kinv = (const int*)d_in[7];
    const int K = in_sizes[6] / 3;

    dim3 b(32, 8);
    dim3 gF(N_ATOMS / 32, 4);
    k_build_fwd<<<gF, b>>>(pos, cell, kfwd, K);
    k_absq<<<(N_ATOMS * D_DIM) / 256, 256>>>(q);

    dim3 gAK((K + 63) / 64, SPLIT_AK);
    k_phaseAK<<<gAK, 256>>>(kvec, K);
    dim3 gAV((K + 31) / 32, 4);
    k_phaseAV<<<gAV, 256>>>(vvec, K);
    k_reduceA<<<(K * D_DIM + 255) / 256, 256>>>(K);

    dim3 gB((K + 127) / 128, N_ATOMS / 128);
    k_phaseB<<<gB, 256>>>(K);
    k_softmax<<<N_ATOMS, 256>>>(K);

    dim3 gD(N_ATOMS / 32, 2);
    k_phaseD<<<gD, 256>>>(pos, cell, kinv, K);
    k_reduceD<<<(N_ATOMS * D_DIM) / 256, 256>>>((float*)d_out);
}